// round 3
// baseline (speedup 1.0000x reference)
#include <cuda_runtime.h>

#define S_DIM 256
#define H_DIM 256
#define W_DIM 256
#define F_DIM 6
#define B_DIM 4096
#define NQ (B_DIM * 4)                       // 16384 queries (b, t, ss/es)
#define YTILE 32
#define NBUCKET (H_DIM * (W_DIM / YTILE))    // 2048
#define CAP 96
#define S_STRIDE (H_DIM * W_DIM * F_DIM)     // floats between consecutive s

__device__ int   g_cnt[NBUCKET];
__device__ int   g_qlist[NBUCKET * CAP];
__device__ float g_qv[NQ];

// ---------------- index build ----------------
__global__ void k_zero() {
    int i = blockIdx.x * blockDim.x + threadIdx.x;
    if (i < NBUCKET) g_cnt[i] = 0;
}

__global__ void k_build(const float* __restrict__ phi) {
    int q = blockIdx.x * blockDim.x + threadIdx.x;
    if (q >= NQ) return;
    int b  = q >> 2;
    int t  = (q >> 1) & 1;
    int es = q & 1;
    const float* p = phi + b * 20 + t * 10;
    int x = (int)p[6 + 2 * es];
    int y = (int)p[7 + 2 * es];
    int bucket = x * (W_DIM / YTILE) + (y >> 5);
    int slot = atomicAdd(&g_cnt[bucket], 1);
    if (slot < CAP) g_qlist[bucket * CAP + slot] = (q << 5) | (y & 31);
}

// ---------------- main: stream tile, fused softmax ----------------
__global__ __launch_bounds__(256)
void k_main(const float* __restrict__ w_lin, const float* __restrict__ succ) {
    __shared__ float tile[YTILE][257];   // [y_local][s], padded: conflict-free

    const int bucket = blockIdx.x;
    int n = g_cnt[bucket];
    if (n == 0) return;
    if (n > CAP) n = CAP;

    const int x  = bucket >> 3;          // W_DIM/YTILE == 8
    const int y0 = (bucket & 7) * YTILE;

    const float w0 = __ldg(w_lin + 0);
    const float w1 = __ldg(w_lin + 1);
    const float w2 = __ldg(w_lin + 2);
    const float w3 = __ldg(w_lin + 3);
    const float w4 = __ldg(w_lin + 4);
    const float w5 = __ldg(w_lin + 5);

    const int warp = threadIdx.x >> 5;   // 0..7
    const int lane = threadIdx.x & 31;   // = y_local

    // Phase 1: stream succ[s, x, y0:y0+32, 0:6] for all s, coalesced per warp.
    // warp w covers s = s0+w and s0+w+8 each iteration (unroll-2 for MLP).
    const float* base = succ + ((size_t)x * W_DIM + (size_t)(y0 + lane)) * F_DIM;
#pragma unroll 4
    for (int s0 = 0; s0 < S_DIM; s0 += 16) {
        const int sA = s0 + warp;
        const float* pA = base + (size_t)sA * S_STRIDE;
        const float* pB = pA + (size_t)8 * S_STRIDE;
        const float2 a0 = __ldcs((const float2*)(pA + 0));
        const float2 a1 = __ldcs((const float2*)(pA + 2));
        const float2 a2 = __ldcs((const float2*)(pA + 4));
        const float2 b0 = __ldcs((const float2*)(pB + 0));
        const float2 b1 = __ldcs((const float2*)(pB + 2));
        const float2 b2 = __ldcs((const float2*)(pB + 4));
        tile[lane][sA] = fmaf(a0.x, w0, fmaf(a0.y, w1,
                         fmaf(a1.x, w2, fmaf(a1.y, w3,
                         fmaf(a2.x, w4, a2.y * w5)))));
        tile[lane][sA + 8] = fmaf(b0.x, w0, fmaf(b0.y, w1,
                             fmaf(b1.x, w2, fmaf(b1.y, w3,
                             fmaf(b2.x, w4, b2.y * w5)))));
    }
    __syncthreads();

    // Phase 2: each warp handles queries i = warp, warp+8, ... in this bucket.
    for (int i = warp; i < n; i += 8) {
        const int e  = g_qlist[bucket * CAP + i];
        const int yl = e & 31;
        const int q  = e >> 5;
        const float* row = tile[yl];

        float v[8];
#pragma unroll
        for (int k = 0; k < 8; k++) v[k] = row[lane + 32 * k];

        float m = v[0];
#pragma unroll
        for (int k = 1; k < 8; k++) m = fmaxf(m, v[k]);
#pragma unroll
        for (int off = 16; off > 0; off >>= 1)
            m = fmaxf(m, __shfl_xor_sync(0xffffffffu, m, off));

        float se = 0.0f, sev = 0.0f;
#pragma unroll
        for (int k = 0; k < 8; k++) {
            const float ex = __expf(v[k] - m);
            se  += ex;
            sev += ex * v[k];
        }
#pragma unroll
        for (int off = 16; off > 0; off >>= 1) {
            se  += __shfl_xor_sync(0xffffffffu, se,  off);
            sev += __shfl_xor_sync(0xffffffffu, sev, off);
        }

        if (lane == 0) g_qv[q] = sev / se;
    }
}

// ---------------- final combine ----------------
__global__ void k_final(const float* __restrict__ phi,
                        const float* __restrict__ w_lin,
                        float* __restrict__ out) {
    int b = blockIdx.x * blockDim.x + threadIdx.x;
    if (b >= B_DIM) return;

    const float w0 = __ldg(w_lin + 0);
    const float w1 = __ldg(w_lin + 1);
    const float w2 = __ldg(w_lin + 2);
    const float w3 = __ldg(w_lin + 3);
    const float w4 = __ldg(w_lin + 4);
    const float w5 = __ldg(w_lin + 5);

    const float* p0 = phi + b * 20;
    const float* p1 = p0 + 10;
    const float pr0 = fmaf(p0[0], w0, fmaf(p0[1], w1, fmaf(p0[2], w2,
                      fmaf(p0[3], w3, fmaf(p0[4], w4, p0[5] * w5)))));
    const float pr1 = fmaf(p1[0], w0, fmaf(p1[1], w1, fmaf(p1[2], w2,
                      fmaf(p1[3], w3, fmaf(p1[4], w4, p1[5] * w5)))));

    // q = b*4 + t*2 + es
    const float vss0 = g_qv[b * 4 + 0];
    const float ves0 = g_qv[b * 4 + 1];
    const float vss1 = g_qv[b * 4 + 2];
    const float ves1 = g_qv[b * 4 + 3];

    const float left_der  = pr0 + (ves0 - vss0);
    const float right_der = pr1 + (ves1 - vss1);
    const float d = left_der - right_der;

    out[b * 2 + 0] = 1.0f / (1.0f + expf(-d));
    out[b * 2 + 1] = 1.0f / (1.0f + expf(d));
}

extern "C" void kernel_launch(void* const* d_in, const int* in_sizes, int n_in,
                              void* d_out, int out_size) {
    const float* phi   = (const float*)d_in[0];  // (B, 2, 10)
    const float* w_lin = (const float*)d_in[1];  // (1, 6)
    const float* succ  = (const float*)d_in[2];  // (S, H, W, F)
    float* out = (float*)d_out;                  // (B, 2, 1)

    k_zero<<<(NBUCKET + 511) / 512, 512>>>();
    k_build<<<(NQ + 255) / 256, 256>>>(phi);
    k_main<<<NBUCKET, 256>>>(w_lin, succ);
    k_final<<<(B_DIM + 255) / 256, 256>>>(phi, w_lin, out);
}

// round 4
// speedup vs baseline: 1.1272x; 1.1272x over previous
#include <cuda_runtime.h>

#define S_DIM 256
#define H_DIM 256
#define W_DIM 256
#define F_DIM 6
#define B_DIM 4096
// stride in floats between consecutive s for fixed (x,y)
#define S_STRIDE (H_DIM * W_DIM * F_DIM)

// One warp per batch element b. Within the warp:
//   lane = ql*8 + k, ql = t*2+es selects the query (t, ss/es), k = s-chunk.
// Thread handles s in [32k, 32k+32) SEQUENTIALLY -> chip-wide the active
// s-window is ~8 planes (12.6 MB), so L2 dedupes the ~2x line-touch overlap.
__global__ __launch_bounds__(128, 6)
void reward_er_kernel(const float* __restrict__ phi,
                      const float* __restrict__ w_lin,
                      const float* __restrict__ succ,
                      float* __restrict__ out) {
    const int warp = threadIdx.x >> 5;
    const int lane = threadIdx.x & 31;
    const int b    = blockIdx.x * 4 + warp;

    const int ql = lane >> 3;   // 0..3 = t*2 + es
    const int k  = lane & 7;    // s chunk id
    const int t  = ql >> 1;
    const int es = ql & 1;

    const float w0 = __ldg(w_lin + 0);
    const float w1 = __ldg(w_lin + 1);
    const float w2 = __ldg(w_lin + 2);
    const float w3 = __ldg(w_lin + 3);
    const float w4 = __ldg(w_lin + 4);
    const float w5 = __ldg(w_lin + 5);

    const float* p = phi + b * 20 + t * 10;   // phi is (B, 2, 10)
    const int x = (int)p[6 + 2 * es];
    const int y = (int)p[7 + 2 * es];

    const float* base = succ + ((size_t)(x * W_DIM + y)) * F_DIM
                             + (size_t)(k * 32) * S_STRIDE;

    // 32 s-values per thread, sequential planes (j = s offset within chunk)
    float v[32];
#pragma unroll
    for (int j = 0; j < 32; j++) {
        const float* ptr = base + (size_t)j * S_STRIDE;
        const float2 a = __ldg((const float2*)(ptr + 0));
        const float2 c = __ldg((const float2*)(ptr + 2));
        const float2 d = __ldg((const float2*)(ptr + 4));
        v[j] = fmaf(a.x, w0, fmaf(a.y, w1,
               fmaf(c.x, w2, fmaf(c.y, w3,
               fmaf(d.x, w4, d.y * w5)))));
    }

    // two-pass softmax-weighted mean over the 256 s values of this query,
    // spread across the 8-lane group (shfl_xor masks <8 stay in-group)
    float m = v[0];
#pragma unroll
    for (int j = 1; j < 32; j++) m = fmaxf(m, v[j]);
#pragma unroll
    for (int off = 4; off > 0; off >>= 1)
        m = fmaxf(m, __shfl_xor_sync(0xffffffffu, m, off));

    float se = 0.0f, sev = 0.0f;
#pragma unroll
    for (int j = 0; j < 32; j++) {
        const float e = __expf(v[j] - m);
        se  += e;
        sev += e * v[j];
    }
#pragma unroll
    for (int off = 4; off > 0; off >>= 1) {
        se  += __shfl_xor_sync(0xffffffffu, se,  off);
        sev += __shfl_xor_sync(0xffffffffu, sev, off);
    }

    const float val = sev / se;  // valid on every lane of the 8-lane group

    // gather the 4 query values: ql0=(t0,ss) ql1=(t0,es) ql2=(t1,ss) ql3=(t1,es)
    const float vss0 = __shfl_sync(0xffffffffu, val, 0);
    const float ves0 = __shfl_sync(0xffffffffu, val, 8);
    const float vss1 = __shfl_sync(0xffffffffu, val, 16);
    const float ves1 = __shfl_sync(0xffffffffu, val, 24);

    if (lane == 0) {
        const float* p0 = phi + b * 20;
        const float* p1 = p0 + 10;
        const float pr0 = fmaf(p0[0], w0, fmaf(p0[1], w1, fmaf(p0[2], w2,
                          fmaf(p0[3], w3, fmaf(p0[4], w4, p0[5] * w5)))));
        const float pr1 = fmaf(p1[0], w0, fmaf(p1[1], w1, fmaf(p1[2], w2,
                          fmaf(p1[3], w3, fmaf(p1[4], w4, p1[5] * w5)))));

        const float left_der  = pr0 + (ves0 - vss0);
        const float right_der = pr1 + (ves1 - vss1);
        const float d = left_der - right_der;

        float2 r;
        r.x = 1.0f / (1.0f + expf(-d));  // sigmoid(d)
        r.y = 1.0f / (1.0f + expf(d));   // sigmoid(-d)
        reinterpret_cast<float2*>(out)[b] = r;
    }
}

extern "C" void kernel_launch(void* const* d_in, const int* in_sizes, int n_in,
                              void* d_out, int out_size) {
    const float* phi   = (const float*)d_in[0];  // (B, 2, 10)
    const float* w_lin = (const float*)d_in[1];  // (1, 6)
    const float* succ  = (const float*)d_in[2];  // (S, H, W, F)
    float* out = (float*)d_out;                  // (B, 2, 1)

    reward_er_kernel<<<B_DIM / 4, 128>>>(phi, w_lin, succ, out);
}

// round 5
// speedup vs baseline: 1.1554x; 1.0250x over previous
#include <cuda_runtime.h>

#define S_DIM 256
#define H_DIM 256
#define W_DIM 256
#define F_DIM 6
#define B_DIM 4096
#define S_STRIDE (H_DIM * W_DIM * F_DIM)   // floats between consecutive s

// One warp per batch element b. lane = ql*8 + k:
//   ql = t*2+es selects the query, k = s-chunk; thread owns s = 32k + j, j=0..31.
// All threads advance j in lockstep (unroll 4 + block sync) -> chip-wide
// instantaneous window ~= 8-16 planes (<=25 MB) so L2 dedupes duplicate lines.
__global__ __launch_bounds__(128, 8)
void reward_er_kernel(const float* __restrict__ phi,
                      const float* __restrict__ w_lin,
                      const float* __restrict__ succ,
                      float* __restrict__ out) {
    const int warp = threadIdx.x >> 5;
    const int lane = threadIdx.x & 31;
    const int b    = blockIdx.x * 4 + warp;

    const int ql = lane >> 3;   // 0..3 = t*2 + es
    const int k  = lane & 7;    // s chunk id
    const int t  = ql >> 1;
    const int es = ql & 1;

    const float w0 = __ldg(w_lin + 0);
    const float w1 = __ldg(w_lin + 1);
    const float w2 = __ldg(w_lin + 2);
    const float w3 = __ldg(w_lin + 3);
    const float w4 = __ldg(w_lin + 4);
    const float w5 = __ldg(w_lin + 5);

    const float* p = phi + b * 20 + t * 10;   // phi is (B, 2, 10)
    const int x = (int)p[6 + 2 * es];
    const int y = (int)p[7 + 2 * es];

    const float* base = succ + ((size_t)(x * W_DIM + y)) * F_DIM
                             + (size_t)(k * 32) * S_STRIDE;

    // online softmax accumulators (no v[32] array -> low regs -> 8 blocks/SM)
    float m = -3.0e38f, se = 0.0f, sev = 0.0f;

    for (int j0 = 0; j0 < 32; j0 += 4) {
#pragma unroll
        for (int u = 0; u < 4; u++) {
            const float* ptr = base + (size_t)(j0 + u) * S_STRIDE;
            const float2 a = __ldg((const float2*)(ptr + 0));
            const float2 c = __ldg((const float2*)(ptr + 2));
            const float2 d = __ldg((const float2*)(ptr + 4));
            const float v = fmaf(a.x, w0, fmaf(a.y, w1,
                            fmaf(c.x, w2, fmaf(c.y, w3,
                            fmaf(d.x, w4, d.y * w5)))));
            const float mo = m;
            m = fmaxf(m, v);
            const float corr = __expf(mo - m);   // exp(-inf)=0 handles first elem
            const float e    = __expf(v - m);
            se  = fmaf(se,  corr, e);
            sev = fmaf(sev, corr, e * v);
        }
        __syncthreads();   // pace all 4 warps: bound intra-block plane drift
    }

    // merge (m, se, sev) across the 8-lane group (masks <8 stay in-group)
#pragma unroll
    for (int off = 4; off > 0; off >>= 1) {
        const float m2   = __shfl_xor_sync(0xffffffffu, m,   off);
        const float se2  = __shfl_xor_sync(0xffffffffu, se,  off);
        const float sev2 = __shfl_xor_sync(0xffffffffu, sev, off);
        const float mm = fmaxf(m, m2);
        const float c1 = __expf(m  - mm);
        const float c2 = __expf(m2 - mm);
        se  = fmaf(se,  c1, se2  * c2);
        sev = fmaf(sev, c1, sev2 * c2);
        m = mm;
    }

    const float val = sev / se;  // valid on every lane of the 8-lane group

    // gather the 4 query values: ql0=(t0,ss) ql1=(t0,es) ql2=(t1,ss) ql3=(t1,es)
    const float vss0 = __shfl_sync(0xffffffffu, val, 0);
    const float ves0 = __shfl_sync(0xffffffffu, val, 8);
    const float vss1 = __shfl_sync(0xffffffffu, val, 16);
    const float ves1 = __shfl_sync(0xffffffffu, val, 24);

    if (lane == 0) {
        const float* p0 = phi + b * 20;
        const float* p1 = p0 + 10;
        const float pr0 = fmaf(p0[0], w0, fmaf(p0[1], w1, fmaf(p0[2], w2,
                          fmaf(p0[3], w3, fmaf(p0[4], w4, p0[5] * w5)))));
        const float pr1 = fmaf(p1[0], w0, fmaf(p1[1], w1, fmaf(p1[2], w2,
                          fmaf(p1[3], w3, fmaf(p1[4], w4, p1[5] * w5)))));

        const float left_der  = pr0 + (ves0 - vss0);
        const float right_der = pr1 + (ves1 - vss1);
        const float d = left_der - right_der;

        float2 r;
        r.x = 1.0f / (1.0f + expf(-d));  // sigmoid(d)
        r.y = 1.0f / (1.0f + expf(d));   // sigmoid(-d)
        reinterpret_cast<float2*>(out)[b] = r;
    }
}

extern "C" void kernel_launch(void* const* d_in, const int* in_sizes, int n_in,
                              void* d_out, int out_size) {
    const float* phi   = (const float*)d_in[0];  // (B, 2, 10)
    const float* w_lin = (const float*)d_in[1];  // (1, 6)
    const float* succ  = (const float*)d_in[2];  // (S, H, W, F)
    float* out = (float*)d_out;                  // (B, 2, 1)

    reward_er_kernel<<<B_DIM / 4, 128>>>(phi, w_lin, succ, out);
}

// round 6
// speedup vs baseline: 1.3275x; 1.1489x over previous
#include <cuda_runtime.h>

#define S_DIM 256
#define H_DIM 256
#define W_DIM 256
#define F_DIM 6
#define B_DIM 4096
#define NQ (B_DIM * 4)          // 16384 queries, q = b*4 + t*2 + es
#define NBIN 4096               // sort key = (x<<4) | (y>>4)
#define S_STRIDE (H_DIM * W_DIM * F_DIM)

__device__ int   g_perm[NQ];
__device__ float g_qv[NQ];

// ---------- single-block counting sort of queries by (x, y/16) ----------
__global__ __launch_bounds__(1024)
void k_prep(const float* __restrict__ phi) {
    __shared__ int bin[NBIN];
    __shared__ int wsum[32];
    const int tid  = threadIdx.x;
    const int lane = tid & 31;
    const int wid  = tid >> 5;

    for (int i = tid; i < NBIN; i += 1024) bin[i] = 0;
    __syncthreads();

    int keys[16];
#pragma unroll
    for (int u = 0; u < 16; u++) {
        const int q  = tid + u * 1024;
        const int b  = q >> 2;
        const int t  = (q >> 1) & 1;
        const int es = q & 1;
        const float* p = phi + b * 20 + t * 10;
        const int x = (int)p[6 + 2 * es];
        const int y = (int)p[7 + 2 * es];
        keys[u] = (x << 4) | (y >> 4);
        atomicAdd(&bin[keys[u]], 1);
    }
    __syncthreads();

    // exclusive scan over bin[4096], 4 consecutive bins per thread
    const int base = tid * 4;
    const int c0 = bin[base], c1 = bin[base + 1];
    const int c2 = bin[base + 2], c3 = bin[base + 3];
    const int tsum = c0 + c1 + c2 + c3;

    int incl = tsum;
#pragma unroll
    for (int off = 1; off < 32; off <<= 1) {
        const int n = __shfl_up_sync(0xffffffffu, incl, off);
        if (lane >= off) incl += n;
    }
    if (lane == 31) wsum[wid] = incl;
    __syncthreads();
    if (wid == 0) {
        const int v = wsum[lane];
        int iv = v;
#pragma unroll
        for (int off = 1; off < 32; off <<= 1) {
            const int n = __shfl_up_sync(0xffffffffu, iv, off);
            if (lane >= off) iv += n;
        }
        wsum[lane] = iv - v;   // exclusive warp offsets
    }
    __syncthreads();

    const int excl = incl - tsum + wsum[wid];
    bin[base]     = excl;
    bin[base + 1] = excl + c0;
    bin[base + 2] = excl + c0 + c1;
    bin[base + 3] = excl + c0 + c1 + c2;
    __syncthreads();

    // scatter: g_perm[pos] = q (order within bin arbitrary -> values unaffected)
#pragma unroll
    for (int u = 0; u < 16; u++) {
        const int q   = tid + u * 1024;
        const int pos = atomicAdd(&bin[keys[u]], 1);
        g_perm[pos] = q;
    }
}

// ---------- main gather: warp handles 4 CONSECUTIVE sorted queries ----------
// lane = ql*8 + k; group ql owns sorted query perm[w*4+ql]; thread owns
// s = 32k + j, j=0..31. Same-line queries sit in the same warp at the same
// step -> the coalescer merges their loads into one line request.
__global__ __launch_bounds__(128, 8)
void k_main(const float* __restrict__ phi,
            const float* __restrict__ w_lin,
            const float* __restrict__ succ) {
    const int warp = threadIdx.x >> 5;
    const int lane = threadIdx.x & 31;
    const int w    = blockIdx.x * 4 + warp;

    const int ql = lane >> 3;
    const int k  = lane & 7;

    const int q  = g_perm[w * 4 + ql];
    const int b  = q >> 2;
    const int t  = (q >> 1) & 1;
    const int es = q & 1;

    const float w0 = __ldg(w_lin + 0);
    const float w1 = __ldg(w_lin + 1);
    const float w2 = __ldg(w_lin + 2);
    const float w3 = __ldg(w_lin + 3);
    const float w4 = __ldg(w_lin + 4);
    const float w5 = __ldg(w_lin + 5);

    const float* p = phi + b * 20 + t * 10;
    const int x = (int)p[6 + 2 * es];
    const int y = (int)p[7 + 2 * es];

    const float* base = succ + ((size_t)(x * W_DIM + y)) * F_DIM
                             + (size_t)(k * 32) * S_STRIDE;

    float m = -3.0e38f, se = 0.0f, sev = 0.0f;

    for (int j0 = 0; j0 < 32; j0 += 4) {
#pragma unroll
        for (int u = 0; u < 4; u++) {
            const float* ptr = base + (size_t)(j0 + u) * S_STRIDE;
            const float2 a = __ldg((const float2*)(ptr + 0));
            const float2 c = __ldg((const float2*)(ptr + 2));
            const float2 d = __ldg((const float2*)(ptr + 4));
            const float v = fmaf(a.x, w0, fmaf(a.y, w1,
                            fmaf(c.x, w2, fmaf(c.y, w3,
                            fmaf(d.x, w4, d.y * w5)))));
            const float mo = m;
            m = fmaxf(m, v);
            const float corr = __expf(mo - m);
            const float e    = __expf(v - m);
            se  = fmaf(se,  corr, e);
            sev = fmaf(sev, corr, e * v);
        }
        __syncthreads();   // pace warps: keep the block's line reuse tight
    }

    // merge (m, se, sev) across the 8-lane group
#pragma unroll
    for (int off = 4; off > 0; off >>= 1) {
        const float m2   = __shfl_xor_sync(0xffffffffu, m,   off);
        const float se2  = __shfl_xor_sync(0xffffffffu, se,  off);
        const float sev2 = __shfl_xor_sync(0xffffffffu, sev, off);
        const float mm = fmaxf(m, m2);
        const float c1 = __expf(m  - mm);
        const float c2 = __expf(m2 - mm);
        se  = fmaf(se,  c1, se2  * c2);
        sev = fmaf(sev, c1, sev2 * c2);
        m = mm;
    }

    if (k == 0) g_qv[q] = sev / se;
}

// ---------- final combine ----------
__global__ void k_final(const float* __restrict__ phi,
                        const float* __restrict__ w_lin,
                        float* __restrict__ out) {
    const int b = blockIdx.x * blockDim.x + threadIdx.x;
    if (b >= B_DIM) return;

    const float w0 = __ldg(w_lin + 0);
    const float w1 = __ldg(w_lin + 1);
    const float w2 = __ldg(w_lin + 2);
    const float w3 = __ldg(w_lin + 3);
    const float w4 = __ldg(w_lin + 4);
    const float w5 = __ldg(w_lin + 5);

    const float* p0 = phi + b * 20;
    const float* p1 = p0 + 10;
    const float pr0 = fmaf(p0[0], w0, fmaf(p0[1], w1, fmaf(p0[2], w2,
                      fmaf(p0[3], w3, fmaf(p0[4], w4, p0[5] * w5)))));
    const float pr1 = fmaf(p1[0], w0, fmaf(p1[1], w1, fmaf(p1[2], w2,
                      fmaf(p1[3], w3, fmaf(p1[4], w4, p1[5] * w5)))));

    const float vss0 = g_qv[b * 4 + 0];
    const float ves0 = g_qv[b * 4 + 1];
    const float vss1 = g_qv[b * 4 + 2];
    const float ves1 = g_qv[b * 4 + 3];

    const float left_der  = pr0 + (ves0 - vss0);
    const float right_der = pr1 + (ves1 - vss1);
    const float d = left_der - right_der;

    float2 r;
    r.x = 1.0f / (1.0f + expf(-d));
    r.y = 1.0f / (1.0f + expf(d));
    reinterpret_cast<float2*>(out)[b] = r;
}

extern "C" void kernel_launch(void* const* d_in, const int* in_sizes, int n_in,
                              void* d_out, int out_size) {
    const float* phi   = (const float*)d_in[0];  // (B, 2, 10)
    const float* w_lin = (const float*)d_in[1];  // (1, 6)
    const float* succ  = (const float*)d_in[2];  // (S, H, W, F)
    float* out = (float*)d_out;                  // (B, 2, 1)

    k_prep<<<1, 1024>>>(phi);
    k_main<<<NQ / 16, 128>>>(phi, w_lin, succ);
    k_final<<<B_DIM / 128, 128>>>(phi, w_lin, out);
}